// round 2
// baseline (speedup 1.0000x reference)
#include <cuda_runtime.h>

#define NN 131072
#define DD 128
#define EE 2097152
#define BBG 16
#define EPSV 1e-5f

// ---------------- device scratch (no allocations allowed) ----------------
__device__ float g_A[NN * DD];    // c1 -> h01 -> ac_h1
__device__ float g_B[NN * DD];    // c2 -> h02 -> ac_h2
__device__ float g_C[NN * DD];    // c3 -> h03 -> ac_h3
__device__ float g_a1[NN * DD];   // a1, later ac_h4
__device__ float g_a2[NN * DD];
__device__ float g_a3[NN * DD];
__device__ float g_agg[NN * DD];  // aggregation scratch
__device__ float g_convw[3 * 3 * DD * DD];  // [conv][tap][in][out]
__device__ float g_stats[12 * DD];
__device__ float g_hg[BBG * 3 * DD];

// ---------------- small kernels ----------------
__global__ void prep_conv_w(const float* __restrict__ w1,
                            const float* __restrict__ w2,
                            const float* __restrict__ w3) {
    int idx = blockIdx.x * blockDim.x + threadIdx.x;  // over 3*DD*DD (t,i,o)
    if (idx >= 3 * DD * DD) return;
    int o = idx % DD;
    int i = (idx / DD) % DD;
    int t = idx / (DD * DD);
    // source layout: w[o, i, t]  (row-major [DD][DD][3])
    g_convw[((0 * 3 + t) * DD + i) * DD + o] = w1[(o * DD + i) * 3 + t];
    g_convw[((1 * 3 + t) * DD + i) * DD + o] = w2[(o * DD + i) * 3 + t];
    g_convw[((2 * 3 + t) * DD + i) * DD + o] = w3[(o * DD + i) * 3 + t];
}

__global__ void zero_buf(float* __restrict__ p, int n4) {
    int i = blockIdx.x * blockDim.x + threadIdx.x;
    int stride = gridDim.x * blockDim.x;
    float4 z = make_float4(0.f, 0.f, 0.f, 0.f);
    for (; i < n4; i += stride) ((float4*)p)[i] = z;
}

__global__ void zero_stats_hg() {
    int i = blockIdx.x * blockDim.x + threadIdx.x;
    if (i < 12 * DD) g_stats[i] = 0.f;
    if (i < BBG * 3 * DD) g_hg[i] = 0.f;
}

// ---------------- dilated conv1d over node axis ----------------
// out[n, o] = sum_t sum_i W[t][i][o] * X[n + (t-1)*dil, i] + bias[o]
__global__ __launch_bounds__(256) void conv1d_kernel(
    const float* __restrict__ X, const float* __restrict__ W,
    const float* __restrict__ bias, float* __restrict__ out, int dil) {
    extern __shared__ float sm[];
    float* sA = sm;              // [ext][132] padded
    float* sW = sm + 70 * 132;   // [128][128]
    const int base = blockIdx.x * 64;
    const int ext = 64 + 2 * dil;
    const int tid = threadIdx.x;

    for (int idx = tid; idx < ext * 32; idx += 256) {
        int r = idx >> 5, c4 = idx & 31;
        int gr = base - dil + r;
        float4 v = make_float4(0.f, 0.f, 0.f, 0.f);
        if (gr >= 0 && gr < NN) v = ((const float4*)X)[gr * 32 + c4];
        ((float4*)(sA + r * 132))[c4] = v;
    }

    const int ty = tid >> 4, tx = tid & 15;
    const int r0 = ty * 4, c0 = tx * 8;
    float acc[4][8];
#pragma unroll
    for (int i = 0; i < 4; i++)
#pragma unroll
        for (int j = 0; j < 8; j++) acc[i][j] = 0.f;

    for (int t = 0; t < 3; t++) {
        __syncthreads();
        for (int idx = tid; idx < DD * 32; idx += 256)
            ((float4*)sW)[idx] = ((const float4*)(W + t * DD * DD))[idx];
        __syncthreads();
        const int sh = t * dil;
#pragma unroll 4
        for (int k = 0; k < DD; k++) {
            float b0[8];
            float4 v0 = *(const float4*)&sW[k * DD + c0];
            float4 v1 = *(const float4*)&sW[k * DD + c0 + 4];
            b0[0] = v0.x; b0[1] = v0.y; b0[2] = v0.z; b0[3] = v0.w;
            b0[4] = v1.x; b0[5] = v1.y; b0[6] = v1.z; b0[7] = v1.w;
#pragma unroll
            for (int i = 0; i < 4; i++) {
                float a = sA[(r0 + i + sh) * 132 + k];
#pragma unroll
                for (int j = 0; j < 8; j++) acc[i][j] = fmaf(a, b0[j], acc[i][j]);
            }
        }
    }

#pragma unroll
    for (int i = 0; i < 4; i++) {
        int n = base + r0 + i;
        float4 o0, o1;
        o0.x = acc[i][0] + bias[c0 + 0]; o0.y = acc[i][1] + bias[c0 + 1];
        o0.z = acc[i][2] + bias[c0 + 2]; o0.w = acc[i][3] + bias[c0 + 3];
        o1.x = acc[i][4] + bias[c0 + 4]; o1.y = acc[i][5] + bias[c0 + 5];
        o1.z = acc[i][6] + bias[c0 + 6]; o1.w = acc[i][7] + bias[c0 + 7];
        ((float4*)(out + n * DD + c0))[0] = o0;
        ((float4*)(out + n * DD + c0 + 4))[0] = o1;
    }
}

// ---------------- GEMM + bias + relu for graph conv: out = relu(A @ W + b) ----------------
// W layout: [in][out] row-major (exactly the dataset layout)
__global__ __launch_bounds__(256) void gemm_bias_relu(
    const float* __restrict__ A, const float* __restrict__ W,
    const float* __restrict__ bias, float* __restrict__ out) {
    extern __shared__ float sm[];
    float* sA = sm;              // [64][132]
    float* sW = sm + 64 * 132;   // [128][128]
    const int base = blockIdx.x * 64;
    const int tid = threadIdx.x;

    for (int idx = tid; idx < 64 * 32; idx += 256) {
        int r = idx >> 5, c4 = idx & 31;
        ((float4*)(sA + r * 132))[c4] = ((const float4*)(A + (base + r) * DD))[c4];
    }
    for (int idx = tid; idx < DD * 32; idx += 256)
        ((float4*)sW)[idx] = ((const float4*)W)[idx];
    __syncthreads();

    const int ty = tid >> 4, tx = tid & 15;
    const int r0 = ty * 4, c0 = tx * 8;
    float acc[4][8];
#pragma unroll
    for (int i = 0; i < 4; i++)
#pragma unroll
        for (int j = 0; j < 8; j++) acc[i][j] = 0.f;

#pragma unroll 4
    for (int k = 0; k < DD; k++) {
        float b0[8];
        float4 v0 = *(const float4*)&sW[k * DD + c0];
        float4 v1 = *(const float4*)&sW[k * DD + c0 + 4];
        b0[0] = v0.x; b0[1] = v0.y; b0[2] = v0.z; b0[3] = v0.w;
        b0[4] = v1.x; b0[5] = v1.y; b0[6] = v1.z; b0[7] = v1.w;
#pragma unroll
        for (int i = 0; i < 4; i++) {
            float a = sA[(r0 + i) * 132 + k];
#pragma unroll
            for (int j = 0; j < 8; j++) acc[i][j] = fmaf(a, b0[j], acc[i][j]);
        }
    }

#pragma unroll
    for (int i = 0; i < 4; i++) {
        int n = base + r0 + i;
        float4 o0, o1;
        o0.x = fmaxf(acc[i][0] + bias[c0 + 0], 0.f);
        o0.y = fmaxf(acc[i][1] + bias[c0 + 1], 0.f);
        o0.z = fmaxf(acc[i][2] + bias[c0 + 2], 0.f);
        o0.w = fmaxf(acc[i][3] + bias[c0 + 3], 0.f);
        o1.x = fmaxf(acc[i][4] + bias[c0 + 4], 0.f);
        o1.y = fmaxf(acc[i][5] + bias[c0 + 5], 0.f);
        o1.z = fmaxf(acc[i][6] + bias[c0 + 6], 0.f);
        o1.w = fmaxf(acc[i][7] + bias[c0 + 7], 0.f);
        ((float4*)(out + n * DD + c0))[0] = o0;
        ((float4*)(out + n * DD + c0 + 4))[0] = o1;
    }
}

// ---------------- BN stats / apply ----------------
__global__ void bn3_stats(const float* __restrict__ c1, const float* __restrict__ c2,
                          const float* __restrict__ c3) {
    const int ch = threadIdx.x;
    const int rows = NN / 512;
    const int r0 = blockIdx.x * rows;
    float s1 = 0, q1 = 0, s2 = 0, q2 = 0, s3 = 0, q3 = 0;
    for (int r = r0; r < r0 + rows; r++) {
        int o = r * DD + ch;
        float v1 = c1[o], v2 = c2[o], v3 = c3[o];
        float x1 = fmaxf(v1, 0.f) + v2;
        float x2 = fmaxf(v2, 0.f) + v3;
        float x3 = fmaxf(v3, 0.f) + v1;
        s1 += x1; q1 = fmaf(x1, x1, q1);
        s2 += x2; q2 = fmaf(x2, x2, q2);
        s3 += x3; q3 = fmaf(x3, x3, q3);
    }
    atomicAdd(&g_stats[0 * DD + ch], s1); atomicAdd(&g_stats[1 * DD + ch], q1);
    atomicAdd(&g_stats[2 * DD + ch], s2); atomicAdd(&g_stats[3 * DD + ch], q2);
    atomicAdd(&g_stats[4 * DD + ch], s3); atomicAdd(&g_stats[5 * DD + ch], q3);
}

__global__ void bn3_apply(float* __restrict__ c1, float* __restrict__ c2,
                          float* __restrict__ c3, const float* __restrict__ g,
                          const float* __restrict__ b) {
    int idx = blockIdx.x * blockDim.x + threadIdx.x;
    int ch = idx & (DD - 1);
    float v1 = c1[idx], v2 = c2[idx], v3 = c3[idx];
    float x1 = fmaxf(v1, 0.f) + v2;
    float x2 = fmaxf(v2, 0.f) + v3;
    float x3 = fmaxf(v3, 0.f) + v1;
    const float inv = 1.f / (float)NN;
    float mu1 = g_stats[0 * DD + ch] * inv;
    float va1 = g_stats[1 * DD + ch] * inv - mu1 * mu1;
    float mu2 = g_stats[2 * DD + ch] * inv;
    float va2 = g_stats[3 * DD + ch] * inv - mu2 * mu2;
    float mu3 = g_stats[4 * DD + ch] * inv;
    float va3 = g_stats[5 * DD + ch] * inv - mu3 * mu3;
    float gg = g[ch], bb = b[ch];
    c1[idx] = (x1 - mu1) * rsqrtf(va1 + EPSV) * gg + bb;
    c2[idx] = (x2 - mu2) * rsqrtf(va2 + EPSV) * gg + bb;
    c3[idx] = (x3 - mu3) * rsqrtf(va3 + EPSV) * gg + bb;
}

__global__ void bn1_stats(const float* __restrict__ x) {
    const int ch = threadIdx.x;
    const int rows = NN / 512;
    const int r0 = blockIdx.x * rows;
    float s = 0, q = 0;
    for (int r = r0; r < r0 + rows; r++) {
        float v = x[r * DD + ch];
        s += v; q = fmaf(v, v, q);
    }
    atomicAdd(&g_stats[ch], s);
    atomicAdd(&g_stats[DD + ch], q);
}

__global__ void bn1_apply(float* __restrict__ x, const float* __restrict__ g,
                          const float* __restrict__ b) {
    int idx = blockIdx.x * blockDim.x + threadIdx.x;
    int ch = idx & (DD - 1);
    const float inv = 1.f / (float)NN;
    float mu = g_stats[ch] * inv;
    float va = g_stats[DD + ch] * inv - mu * mu;
    x[idx] = (x[idx] - mu) * rsqrtf(va + EPSV) * g[ch] + b[ch];
}

// ---------------- edge scatter: agg[dst] += h[src] * ew ----------------
__global__ __launch_bounds__(256) void scatter_edges(
    const float* __restrict__ H, const int* __restrict__ src,
    const int* __restrict__ dst, const float* __restrict__ ew,
    float* __restrict__ agg) {
    int e = blockIdx.x * 8 + (threadIdx.x >> 5);
    if (e >= EE) return;
    int lane = threadIdx.x & 31;
    int s = src[e];
    int d = dst[e];
    float w = ew[e];
    float4 v = ((const float4*)H)[s * 32 + lane];
    v.x *= w; v.y *= w; v.z *= w; v.w *= w;
    atomicAdd(((float4*)agg) + d * 32 + lane, v);  // sm_90+ vector red
}

// ---------------- press conv (1,3,3) over channel/spatial dims ----------------
__global__ void press_kernel(const float* __restrict__ a1, const float* __restrict__ a2,
                             const float* __restrict__ a3, const float* __restrict__ pw,
                             const float* __restrict__ pb, float* __restrict__ out) {
    int idx = blockIdx.x * blockDim.x + threadIdx.x;
    int n = idx >> 7, d = idx & 127;
    float w00 = pw[0], w01 = pw[1], w02 = pw[2];
    float w10 = pw[3], w11 = pw[4], w12 = pw[5];
    float w20 = pw[6], w21 = pw[7], w22 = pw[8];
    const float* p1 = a1 + n * DD;
    const float* p2 = a2 + n * DD;
    const float* p3 = a3 + n * DD;
    float acc = pb[0];
    if (d > 0) acc += w00 * p1[d - 1] + w10 * p2[d - 1] + w20 * p3[d - 1];
    acc += w01 * p1[d] + w11 * p2[d] + w21 * p3[d];
    if (d < 127) acc += w02 * p1[d + 1] + w12 * p2[d + 1] + w22 * p3[d + 1];
    out[idx] = acc;
}

// ---------------- per-graph pooling (node_gid sorted) ----------------
__global__ void pool_kernel(const float* __restrict__ h2, const float* __restrict__ h3,
                            const float* __restrict__ h4, const int* __restrict__ gid) {
    const int ch = threadIdx.x;
    const int rows = NN / 512;
    const int r0 = blockIdx.x * rows;
    int cur = gid[r0];
    float s2 = 0, s3 = 0, s4 = 0;
    for (int r = r0; r < r0 + rows; r++) {
        int g = gid[r];
        if (g != cur) {
            atomicAdd(&g_hg[cur * 3 * DD + ch], s2);
            atomicAdd(&g_hg[cur * 3 * DD + DD + ch], s3);
            atomicAdd(&g_hg[cur * 3 * DD + 2 * DD + ch], s4);
            s2 = s3 = s4 = 0;
            cur = g;
        }
        int o = r * DD + ch;
        s2 += h2[o]; s3 += h3[o]; s4 += h4[o];
    }
    atomicAdd(&g_hg[cur * 3 * DD + ch], s2);
    atomicAdd(&g_hg[cur * 3 * DD + DD + ch], s3);
    atomicAdd(&g_hg[cur * 3 * DD + 2 * DD + ch], s4);
}

// ---------------- final classifier ----------------
__global__ void classify(const float* __restrict__ cl1w, const float* __restrict__ cl1b,
                         const float* __restrict__ cl2w, const float* __restrict__ cl2b,
                         float* __restrict__ out) {
    __shared__ float mid[DD];
    int t = threadIdx.x;
    for (int b = 0; b < BBG; b++) {
        float acc = cl1b[t];
        for (int k = 0; k < 3 * DD; k++) acc = fmaf(g_hg[b * 3 * DD + k], cl1w[t * 3 * DD + k], acc);
        mid[t] = acc;
        __syncthreads();
        if (t < 5) {
            float o = cl2b[t];
            for (int k = 0; k < DD; k++) o = fmaf(mid[k], cl2w[t * DD + k], o);
            out[b * 5 + t] = o;
        }
        __syncthreads();
    }
}

// ---------------- host launch ----------------
extern "C" void kernel_launch(void* const* d_in, const int* in_sizes, int n_in,
                              void* d_out, int out_size) {
    // robust to presence/absence of the num_graphs scalar at slot 5
    int o = (in_sizes[5] == 1) ? 6 : 5;
    const float* h   = (const float*)d_in[0];
    const float* ew  = (const float*)d_in[1];
    const int*   src = (const int*)d_in[2];
    const int*   dst = (const int*)d_in[3];
    const int*   gid = (const int*)d_in[4];
    const float* c1w = (const float*)d_in[o + 0];
    const float* c1b = (const float*)d_in[o + 1];
    const float* c2w = (const float*)d_in[o + 2];
    const float* c2b = (const float*)d_in[o + 3];
    const float* c3w = (const float*)d_in[o + 4];
    const float* c3b = (const float*)d_in[o + 5];
    const float* pw  = (const float*)d_in[o + 6];
    const float* pb  = (const float*)d_in[o + 7];
    const float* g11w = (const float*)d_in[o + 8];
    const float* g11b = (const float*)d_in[o + 9];
    const float* g12w = (const float*)d_in[o + 10];
    const float* g12b = (const float*)d_in[o + 11];
    const float* g13w = (const float*)d_in[o + 12];
    const float* g13b = (const float*)d_in[o + 13];
    const float* g2w  = (const float*)d_in[o + 14];
    const float* g2b  = (const float*)d_in[o + 15];
    const float* g3w  = (const float*)d_in[o + 16];
    const float* g3b  = (const float*)d_in[o + 17];
    const float* g4w  = (const float*)d_in[o + 18];
    const float* g4b  = (const float*)d_in[o + 19];
    const float* bng  = (const float*)d_in[o + 20];
    const float* bnb  = (const float*)d_in[o + 21];
    const float* cl1w = (const float*)d_in[o + 22];
    const float* cl1b = (const float*)d_in[o + 23];
    const float* cl2w = (const float*)d_in[o + 24];
    const float* cl2b = (const float*)d_in[o + 25];
    float* out = (float*)d_out;

    float *A, *B, *C, *a1, *a2, *a3, *agg, *convw;
    cudaGetSymbolAddress((void**)&A, g_A);
    cudaGetSymbolAddress((void**)&B, g_B);
    cudaGetSymbolAddress((void**)&C, g_C);
    cudaGetSymbolAddress((void**)&a1, g_a1);
    cudaGetSymbolAddress((void**)&a2, g_a2);
    cudaGetSymbolAddress((void**)&a3, g_a3);
    cudaGetSymbolAddress((void**)&agg, g_agg);
    cudaGetSymbolAddress((void**)&convw, g_convw);

    const int CONV_SMEM = (70 * 132 + DD * DD) * 4;
    const int GEMM_SMEM = (64 * 132 + DD * DD) * 4;
    cudaFuncSetAttribute(conv1d_kernel, cudaFuncAttributeMaxDynamicSharedMemorySize, CONV_SMEM);
    cudaFuncSetAttribute(gemm_bias_relu, cudaFuncAttributeMaxDynamicSharedMemorySize, GEMM_SMEM);

    prep_conv_w<<<(3 * DD * DD + 255) / 256, 256>>>(c1w, c2w, c3w);
    conv1d_kernel<<<NN / 64, 256, CONV_SMEM>>>(h, convw + 0 * 3 * DD * DD, c1b, A, 1);
    conv1d_kernel<<<NN / 64, 256, CONV_SMEM>>>(h, convw + 1 * 3 * DD * DD, c2b, B, 2);
    conv1d_kernel<<<NN / 64, 256, CONV_SMEM>>>(h, convw + 2 * 3 * DD * DD, c3b, C, 3);

    zero_stats_hg<<<24, 256>>>();
    bn3_stats<<<512, DD>>>(A, B, C);
    bn3_apply<<<NN * DD / 256, 256>>>(A, B, C, bng, bnb);

#define GCONV(IN, W, BIAS, OUT)                                        \
    zero_buf<<<2048, 256>>>(agg, NN * DD / 4);                         \
    scatter_edges<<<EE / 8, 256>>>(IN, src, dst, ew, agg);             \
    gemm_bias_relu<<<NN / 64, 256, GEMM_SMEM>>>(agg, W, BIAS, OUT);

    GCONV(A, g11w, g11b, a1)
    GCONV(B, g12w, g12b, a2)
    GCONV(C, g13w, g13b, a3)

    press_kernel<<<NN * DD / 256, 256>>>(a1, a2, a3, pw, pb, A);
    zero_stats_hg<<<24, 256>>>();
    bn1_stats<<<512, DD>>>(A);
    bn1_apply<<<NN * DD / 256, 256>>>(A, bng, bnb);

    GCONV(A, g2w, g2b, B)   // ac_h2
    GCONV(B, g3w, g3b, C)   // ac_h3
    GCONV(C, g4w, g4b, a1)  // ac_h4

    pool_kernel<<<512, DD>>>(B, C, a1, gid);
    classify<<<1, DD>>>(cl1w, cl1b, cl2w, cl2b, out);
#undef GCONV
}

// round 3
// speedup vs baseline: 1.2490x; 1.2490x over previous
#include <cuda_runtime.h>

#define NN 131072
#define DD 128
#define EE 2097152
#define BBG 16
#define EPSV 1e-5f

#define SA_S 68   // padded stride for sA [row][k] chunk (64 k + pad)

// ---------------- device scratch (no allocations allowed) ----------------
__device__ float g_A[NN * DD];    // c1 -> h01 -> ac_h1
__device__ float g_B[NN * DD];    // c2 -> h02 -> ac_h2
__device__ float g_C[NN * DD];    // c3 -> h03 -> ac_h3
__device__ float g_a1[NN * DD];   // a1, later ac_h4
__device__ float g_a2[NN * DD];
__device__ float g_a3[NN * DD];
__device__ float g_agg[NN * DD];  // aggregation scratch
__device__ float g_convw[3 * 3 * DD * DD];  // [conv][tap][in][out]
__device__ float g_stats[12 * DD];
__device__ float g_hg[BBG * 3 * DD];

// ---------------- small kernels ----------------
__global__ void prep_conv_w(const float* __restrict__ w1,
                            const float* __restrict__ w2,
                            const float* __restrict__ w3) {
    int idx = blockIdx.x * blockDim.x + threadIdx.x;  // over 3*DD*DD (t,i,o)
    if (idx >= 3 * DD * DD) return;
    int o = idx % DD;
    int i = (idx / DD) % DD;
    int t = idx / (DD * DD);
    // source layout: w[o, i, t]  (row-major [DD][DD][3])
    g_convw[((0 * 3 + t) * DD + i) * DD + o] = w1[(o * DD + i) * 3 + t];
    g_convw[((1 * 3 + t) * DD + i) * DD + o] = w2[(o * DD + i) * 3 + t];
    g_convw[((2 * 3 + t) * DD + i) * DD + o] = w3[(o * DD + i) * 3 + t];
}

__global__ void zero_buf(float* __restrict__ p, int n4) {
    int i = blockIdx.x * blockDim.x + threadIdx.x;
    int stride = gridDim.x * blockDim.x;
    float4 z = make_float4(0.f, 0.f, 0.f, 0.f);
    for (; i < n4; i += stride) ((float4*)p)[i] = z;
}

__global__ void zero_stats_hg() {
    int i = blockIdx.x * blockDim.x + threadIdx.x;
    if (i < 12 * DD) g_stats[i] = 0.f;
    if (i < BBG * 3 * DD) g_hg[i] = 0.f;
}

// ---------------- packed f32x2 GEMM core ----------------
// 128x128 block tile, 256 threads, 8x8 per thread, K processed in 64-chunks.
// acc[i][j] is a packed f32x2 pair for columns (c0+2j, c0+2j+1).
__device__ __forceinline__ void mm_chunk(const float* __restrict__ sA,
                                         const float* __restrict__ sB,
                                         unsigned long long acc[8][4],
                                         int r0, int c0) {
#pragma unroll 8
    for (int k = 0; k < 64; k++) {
        ulonglong2 b01 = *(const ulonglong2*)(sB + k * 128 + c0);
        ulonglong2 b23 = *(const ulonglong2*)(sB + k * 128 + c0 + 4);
        unsigned long long bp0 = b01.x, bp1 = b01.y, bp2 = b23.x, bp3 = b23.y;
#pragma unroll
        for (int i = 0; i < 8; i++) {
            float a = sA[(r0 + i) * SA_S + k];
            unsigned long long aa;
            asm("mov.b64 %0, {%1, %1};" : "=l"(aa) : "f"(a));
            asm("fma.rn.f32x2 %0, %1, %2, %0;" : "+l"(acc[i][0]) : "l"(aa), "l"(bp0));
            asm("fma.rn.f32x2 %0, %1, %2, %0;" : "+l"(acc[i][1]) : "l"(aa), "l"(bp1));
            asm("fma.rn.f32x2 %0, %1, %2, %0;" : "+l"(acc[i][2]) : "l"(aa), "l"(bp2));
            asm("fma.rn.f32x2 %0, %1, %2, %0;" : "+l"(acc[i][3]) : "l"(aa), "l"(bp3));
        }
    }
}

// load 128 rows x 64 k of A (rows guaranteed in range) into sA[row][k]
__device__ __forceinline__ void load_sA(float* __restrict__ sA,
                                        const float* __restrict__ A,
                                        int base_row, int k0, int tid) {
#pragma unroll
    for (int p = 0; p < 8; p++) {
        int idx = p * 256 + tid;
        int row = idx >> 4, kq = idx & 15;
        float4 v = ((const float4*)(A + (base_row + row) * DD + k0))[kq];
        *(float4*)(sA + row * SA_S + kq * 4) = v;
    }
}

// guarded version (rows may be out of [0, NN))
__device__ __forceinline__ void load_sA_g(float* __restrict__ sA,
                                          const float* __restrict__ A,
                                          int base_row, int k0, int tid) {
#pragma unroll
    for (int p = 0; p < 8; p++) {
        int idx = p * 256 + tid;
        int row = idx >> 4, kq = idx & 15;
        int gr = base_row + row;
        float4 v = make_float4(0.f, 0.f, 0.f, 0.f);
        if (gr >= 0 && gr < NN) v = ((const float4*)(A + gr * DD + k0))[kq];
        *(float4*)(sA + row * SA_S + kq * 4) = v;
    }
}

// load 64 k-rows x 128 cols of W into sB[k][col] (dense, stride 128)
__device__ __forceinline__ void load_sB(float* __restrict__ sB,
                                        const float* __restrict__ W,
                                        int k0, int tid) {
#pragma unroll
    for (int p = 0; p < 8; p++) {
        int idx = p * 256 + tid;
        int kr = idx >> 5, c4 = idx & 31;
        ((float4*)(sB + kr * 128))[c4] = ((const float4*)(W + (k0 + kr) * DD))[c4];
    }
}

__device__ __forceinline__ void epilogue(unsigned long long acc[8][4],
                                         const float* __restrict__ bias,
                                         float* __restrict__ out,
                                         int base, int r0, int c0, int relu) {
    float4 bv0 = *(const float4*)(bias + c0);
    float4 bv1 = *(const float4*)(bias + c0 + 4);
    float bb[8] = {bv0.x, bv0.y, bv0.z, bv0.w, bv1.x, bv1.y, bv1.z, bv1.w};
#pragma unroll
    for (int i = 0; i < 8; i++) {
        float v[8];
#pragma unroll
        for (int j = 0; j < 4; j++) {
            float lo, hi;
            asm("mov.b64 {%0, %1}, %2;" : "=f"(lo), "=f"(hi) : "l"(acc[i][j]));
            v[2 * j] = lo; v[2 * j + 1] = hi;
        }
        float4 o0, o1;
        if (relu) {
            o0.x = fmaxf(v[0] + bb[0], 0.f); o0.y = fmaxf(v[1] + bb[1], 0.f);
            o0.z = fmaxf(v[2] + bb[2], 0.f); o0.w = fmaxf(v[3] + bb[3], 0.f);
            o1.x = fmaxf(v[4] + bb[4], 0.f); o1.y = fmaxf(v[5] + bb[5], 0.f);
            o1.z = fmaxf(v[6] + bb[6], 0.f); o1.w = fmaxf(v[7] + bb[7], 0.f);
        } else {
            o0.x = v[0] + bb[0]; o0.y = v[1] + bb[1];
            o0.z = v[2] + bb[2]; o0.w = v[3] + bb[3];
            o1.x = v[4] + bb[4]; o1.y = v[5] + bb[5];
            o1.z = v[6] + bb[6]; o1.w = v[7] + bb[7];
        }
        float* po = out + (base + r0 + i) * DD + c0;
        ((float4*)po)[0] = o0;
        ((float4*)(po + 4))[0] = o1;
    }
}

// out = [relu](A @ W + b), A:[NN,128] rows in-range, W:[128,128] row-major [in][out]
__global__ __launch_bounds__(256, 2) void gemm128_f2(
    const float* __restrict__ A, const float* __restrict__ W,
    const float* __restrict__ bias, float* __restrict__ out, int relu) {
    extern __shared__ float sm[];
    float* sA = sm;                  // [128][SA_S]
    float* sB = sm + 128 * SA_S;     // [64][128]
    const int tid = threadIdx.x;
    const int base = blockIdx.x * 128;
    const int ty = tid >> 4, tx = tid & 15;
    const int r0 = ty * 8, c0 = tx * 8;

    unsigned long long acc[8][4];
#pragma unroll
    for (int i = 0; i < 8; i++)
#pragma unroll
        for (int j = 0; j < 4; j++) acc[i][j] = 0ull;

#pragma unroll
    for (int kc = 0; kc < 2; kc++) {
        load_sA(sA, A, base, kc * 64, tid);
        load_sB(sB, W, kc * 64, tid);
        __syncthreads();
        mm_chunk(sA, sB, acc, r0, c0);
        __syncthreads();
    }
    epilogue(acc, bias, out, base, r0, c0, relu);
}

// dilated conv1d as 3 accumulated shifted GEMMs; W3 = [3][128][128] prepped [tap][in][out]
__global__ __launch_bounds__(256, 2) void conv128_f2(
    const float* __restrict__ X, const float* __restrict__ W3,
    const float* __restrict__ bias, float* __restrict__ out, int dil) {
    extern __shared__ float sm[];
    float* sA = sm;
    float* sB = sm + 128 * SA_S;
    const int tid = threadIdx.x;
    const int base = blockIdx.x * 128;
    const int ty = tid >> 4, tx = tid & 15;
    const int r0 = ty * 8, c0 = tx * 8;

    unsigned long long acc[8][4];
#pragma unroll
    for (int i = 0; i < 8; i++)
#pragma unroll
        for (int j = 0; j < 4; j++) acc[i][j] = 0ull;

    for (int tp = 0; tp < 3; tp++) {
        const int shift = (tp - 1) * dil;
        const float* Wt = W3 + tp * DD * DD;
#pragma unroll
        for (int kc = 0; kc < 2; kc++) {
            load_sA_g(sA, X, base + shift, kc * 64, tid);
            load_sB(sB, Wt, kc * 64, tid);
            __syncthreads();
            mm_chunk(sA, sB, acc, r0, c0);
            __syncthreads();
        }
    }
    epilogue(acc, bias, out, base, r0, c0, 0);
}

// ---------------- BN stats / apply ----------------
__global__ void bn3_stats(const float* __restrict__ c1, const float* __restrict__ c2,
                          const float* __restrict__ c3) {
    const int ch = threadIdx.x;
    const int rows = NN / 512;
    const int r0 = blockIdx.x * rows;
    float s1 = 0, q1 = 0, s2 = 0, q2 = 0, s3 = 0, q3 = 0;
    for (int r = r0; r < r0 + rows; r++) {
        int o = r * DD + ch;
        float v1 = c1[o], v2 = c2[o], v3 = c3[o];
        float x1 = fmaxf(v1, 0.f) + v2;
        float x2 = fmaxf(v2, 0.f) + v3;
        float x3 = fmaxf(v3, 0.f) + v1;
        s1 += x1; q1 = fmaf(x1, x1, q1);
        s2 += x2; q2 = fmaf(x2, x2, q2);
        s3 += x3; q3 = fmaf(x3, x3, q3);
    }
    atomicAdd(&g_stats[0 * DD + ch], s1); atomicAdd(&g_stats[1 * DD + ch], q1);
    atomicAdd(&g_stats[2 * DD + ch], s2); atomicAdd(&g_stats[3 * DD + ch], q2);
    atomicAdd(&g_stats[4 * DD + ch], s3); atomicAdd(&g_stats[5 * DD + ch], q3);
}

__global__ void bn3_apply(float* __restrict__ c1, float* __restrict__ c2,
                          float* __restrict__ c3, const float* __restrict__ g,
                          const float* __restrict__ b) {
    int idx = blockIdx.x * blockDim.x + threadIdx.x;
    int ch = idx & (DD - 1);
    float v1 = c1[idx], v2 = c2[idx], v3 = c3[idx];
    float x1 = fmaxf(v1, 0.f) + v2;
    float x2 = fmaxf(v2, 0.f) + v3;
    float x3 = fmaxf(v3, 0.f) + v1;
    const float inv = 1.f / (float)NN;
    float mu1 = g_stats[0 * DD + ch] * inv;
    float va1 = g_stats[1 * DD + ch] * inv - mu1 * mu1;
    float mu2 = g_stats[2 * DD + ch] * inv;
    float va2 = g_stats[3 * DD + ch] * inv - mu2 * mu2;
    float mu3 = g_stats[4 * DD + ch] * inv;
    float va3 = g_stats[5 * DD + ch] * inv - mu3 * mu3;
    float gg = g[ch], bb = b[ch];
    c1[idx] = (x1 - mu1) * rsqrtf(va1 + EPSV) * gg + bb;
    c2[idx] = (x2 - mu2) * rsqrtf(va2 + EPSV) * gg + bb;
    c3[idx] = (x3 - mu3) * rsqrtf(va3 + EPSV) * gg + bb;
}

__global__ void bn1_stats(const float* __restrict__ x) {
    const int ch = threadIdx.x;
    const int rows = NN / 512;
    const int r0 = blockIdx.x * rows;
    float s = 0, q = 0;
    for (int r = r0; r < r0 + rows; r++) {
        float v = x[r * DD + ch];
        s += v; q = fmaf(v, v, q);
    }
    atomicAdd(&g_stats[ch], s);
    atomicAdd(&g_stats[DD + ch], q);
}

__global__ void bn1_apply(float* __restrict__ x, const float* __restrict__ g,
                          const float* __restrict__ b) {
    int idx = blockIdx.x * blockDim.x + threadIdx.x;
    int ch = idx & (DD - 1);
    const float inv = 1.f / (float)NN;
    float mu = g_stats[ch] * inv;
    float va = g_stats[DD + ch] * inv - mu * mu;
    x[idx] = (x[idx] - mu) * rsqrtf(va + EPSV) * g[ch] + b[ch];
}

// ---------------- edge scatter: agg[dst] += h[src] * ew ----------------
__global__ __launch_bounds__(256) void scatter_edges(
    const float* __restrict__ H, const int* __restrict__ src,
    const int* __restrict__ dst, const float* __restrict__ ew,
    float* __restrict__ agg) {
    int e = blockIdx.x * 8 + (threadIdx.x >> 5);
    if (e >= EE) return;
    int lane = threadIdx.x & 31;
    int s = src[e];
    int d = dst[e];
    float w = ew[e];
    float4 v = ((const float4*)H)[s * 32 + lane];
    v.x *= w; v.y *= w; v.z *= w; v.w *= w;
    atomicAdd(((float4*)agg) + d * 32 + lane, v);  // sm_90+ vector red
}

// ---------------- press conv (1,3,3) over channel/spatial dims ----------------
__global__ void press_kernel(const float* __restrict__ a1, const float* __restrict__ a2,
                             const float* __restrict__ a3, const float* __restrict__ pw,
                             const float* __restrict__ pb, float* __restrict__ out) {
    int idx = blockIdx.x * blockDim.x + threadIdx.x;
    int n = idx >> 7, d = idx & 127;
    float w00 = pw[0], w01 = pw[1], w02 = pw[2];
    float w10 = pw[3], w11 = pw[4], w12 = pw[5];
    float w20 = pw[6], w21 = pw[7], w22 = pw[8];
    const float* p1 = a1 + n * DD;
    const float* p2 = a2 + n * DD;
    const float* p3 = a3 + n * DD;
    float acc = pb[0];
    if (d > 0) acc += w00 * p1[d - 1] + w10 * p2[d - 1] + w20 * p3[d - 1];
    acc += w01 * p1[d] + w11 * p2[d] + w21 * p3[d];
    if (d < 127) acc += w02 * p1[d + 1] + w12 * p2[d + 1] + w22 * p3[d + 1];
    out[idx] = acc;
}

// ---------------- per-graph pooling (node_gid sorted) ----------------
__global__ void pool_kernel(const float* __restrict__ h2, const float* __restrict__ h3,
                            const float* __restrict__ h4, const int* __restrict__ gid) {
    const int ch = threadIdx.x;
    const int rows = NN / 512;
    const int r0 = blockIdx.x * rows;
    int cur = gid[r0];
    float s2 = 0, s3 = 0, s4 = 0;
    for (int r = r0; r < r0 + rows; r++) {
        int g = gid[r];
        if (g != cur) {
            atomicAdd(&g_hg[cur * 3 * DD + ch], s2);
            atomicAdd(&g_hg[cur * 3 * DD + DD + ch], s3);
            atomicAdd(&g_hg[cur * 3 * DD + 2 * DD + ch], s4);
            s2 = s3 = s4 = 0;
            cur = g;
        }
        int o = r * DD + ch;
        s2 += h2[o]; s3 += h3[o]; s4 += h4[o];
    }
    atomicAdd(&g_hg[cur * 3 * DD + ch], s2);
    atomicAdd(&g_hg[cur * 3 * DD + DD + ch], s3);
    atomicAdd(&g_hg[cur * 3 * DD + 2 * DD + ch], s4);
}

// ---------------- final classifier ----------------
__global__ void classify(const float* __restrict__ cl1w, const float* __restrict__ cl1b,
                         const float* __restrict__ cl2w, const float* __restrict__ cl2b,
                         float* __restrict__ out) {
    __shared__ float mid[DD];
    int t = threadIdx.x;
    for (int b = 0; b < BBG; b++) {
        float acc = cl1b[t];
        for (int k = 0; k < 3 * DD; k++) acc = fmaf(g_hg[b * 3 * DD + k], cl1w[t * 3 * DD + k], acc);
        mid[t] = acc;
        __syncthreads();
        if (t < 5) {
            float o = cl2b[t];
            for (int k = 0; k < DD; k++) o = fmaf(mid[k], cl2w[t * DD + k], o);
            out[b * 5 + t] = o;
        }
        __syncthreads();
    }
}

// ---------------- host launch ----------------
extern "C" void kernel_launch(void* const* d_in, const int* in_sizes, int n_in,
                              void* d_out, int out_size) {
    // robust to presence/absence of the num_graphs scalar at slot 5
    int o = (in_sizes[5] == 1) ? 6 : 5;
    const float* h   = (const float*)d_in[0];
    const float* ew  = (const float*)d_in[1];
    const int*   src = (const int*)d_in[2];
    const int*   dst = (const int*)d_in[3];
    const int*   gid = (const int*)d_in[4];
    const float* c1w = (const float*)d_in[o + 0];
    const float* c1b = (const float*)d_in[o + 1];
    const float* c2w = (const float*)d_in[o + 2];
    const float* c2b = (const float*)d_in[o + 3];
    const float* c3w = (const float*)d_in[o + 4];
    const float* c3b = (const float*)d_in[o + 5];
    const float* pw  = (const float*)d_in[o + 6];
    const float* pb  = (const float*)d_in[o + 7];
    const float* g11w = (const float*)d_in[o + 8];
    const float* g11b = (const float*)d_in[o + 9];
    const float* g12w = (const float*)d_in[o + 10];
    const float* g12b = (const float*)d_in[o + 11];
    const float* g13w = (const float*)d_in[o + 12];
    const float* g13b = (const float*)d_in[o + 13];
    const float* g2w  = (const float*)d_in[o + 14];
    const float* g2b  = (const float*)d_in[o + 15];
    const float* g3w  = (const float*)d_in[o + 16];
    const float* g3b  = (const float*)d_in[o + 17];
    const float* g4w  = (const float*)d_in[o + 18];
    const float* g4b  = (const float*)d_in[o + 19];
    const float* bng  = (const float*)d_in[o + 20];
    const float* bnb  = (const float*)d_in[o + 21];
    const float* cl1w = (const float*)d_in[o + 22];
    const float* cl1b = (const float*)d_in[o + 23];
    const float* cl2w = (const float*)d_in[o + 24];
    const float* cl2b = (const float*)d_in[o + 25];
    float* out = (float*)d_out;

    float *A, *B, *C, *a1, *a2, *a3, *agg, *convw;
    cudaGetSymbolAddress((void**)&A, g_A);
    cudaGetSymbolAddress((void**)&B, g_B);
    cudaGetSymbolAddress((void**)&C, g_C);
    cudaGetSymbolAddress((void**)&a1, g_a1);
    cudaGetSymbolAddress((void**)&a2, g_a2);
    cudaGetSymbolAddress((void**)&a3, g_a3);
    cudaGetSymbolAddress((void**)&agg, g_agg);
    cudaGetSymbolAddress((void**)&convw, g_convw);

    const int MM_SMEM = (128 * SA_S + 64 * 128) * 4;
    cudaFuncSetAttribute(gemm128_f2, cudaFuncAttributeMaxDynamicSharedMemorySize, MM_SMEM);
    cudaFuncSetAttribute(conv128_f2, cudaFuncAttributeMaxDynamicSharedMemorySize, MM_SMEM);

    prep_conv_w<<<(3 * DD * DD + 255) / 256, 256>>>(c1w, c2w, c3w);
    conv128_f2<<<NN / 128, 256, MM_SMEM>>>(h, convw + 0 * 3 * DD * DD, c1b, A, 1);
    conv128_f2<<<NN / 128, 256, MM_SMEM>>>(h, convw + 1 * 3 * DD * DD, c2b, B, 2);
    conv128_f2<<<NN / 128, 256, MM_SMEM>>>(h, convw + 2 * 3 * DD * DD, c3b, C, 3);

    zero_stats_hg<<<24, 256>>>();
    bn3_stats<<<512, DD>>>(A, B, C);
    bn3_apply<<<NN * DD / 256, 256>>>(A, B, C, bng, bnb);

#define GCONV(IN, W, BIAS, OUT)                                        \
    zero_buf<<<2048, 256>>>(agg, NN * DD / 4);                         \
    scatter_edges<<<EE / 8, 256>>>(IN, src, dst, ew, agg);             \
    gemm128_f2<<<NN / 128, 256, MM_SMEM>>>(agg, W, BIAS, OUT, 1);

    GCONV(A, g11w, g11b, a1)
    GCONV(B, g12w, g12b, a2)
    GCONV(C, g13w, g13b, a3)

    press_kernel<<<NN * DD / 256, 256>>>(a1, a2, a3, pw, pb, A);
    zero_stats_hg<<<24, 256>>>();
    bn1_stats<<<512, DD>>>(A);
    bn1_apply<<<NN * DD / 256, 256>>>(A, bng, bnb);

    GCONV(A, g2w, g2b, B)   // ac_h2
    GCONV(B, g3w, g3b, C)   // ac_h3
    GCONV(C, g4w, g4b, a1)  // ac_h4

    pool_kernel<<<512, DD>>>(B, C, a1, gid);
    classify<<<1, DD>>>(cl1w, cl1b, cl2w, cl2b, out);
#undef GCONV
}

// round 4
// speedup vs baseline: 1.7323x; 1.3870x over previous
#include <cuda_runtime.h>

#define NN 131072
#define DD 128
#define EE 2097152
#define BBG 16
#define EPSV 1e-5f

#define SA_S 68   // padded stride for sA [row][k] chunk (64 k + pad)

// ---------------- device scratch (no allocations allowed) ----------------
__device__ float g_A[NN * DD];    // c1 -> h01 -> ac_h1
__device__ float g_B[NN * DD];    // c2 -> h02 -> ac_h2
__device__ float g_C[NN * DD];    // c3 -> h03 -> ac_h3
__device__ float g_a1[NN * DD];   // a1, later ac_h4
__device__ float g_a2[NN * DD];
__device__ float g_a3[NN * DD];
__device__ float g_agg[NN * DD];  // aggregation scratch
__device__ float g_convw[3 * 3 * DD * DD];  // [conv][tap][in][out]
__device__ float g_stats[12 * DD];
__device__ float g_hg[BBG * 3 * DD];
// CSR scratch
__device__ uint2 g_meta[EE];      // (src, bits(w)) binned by dst
__device__ int g_deg[NN];
__device__ int g_off[NN + 1];
__device__ int g_cur[NN];
__device__ int g_part[128];

// ---------------- small kernels ----------------
__global__ void prep_conv_w(const float* __restrict__ w1,
                            const float* __restrict__ w2,
                            const float* __restrict__ w3) {
    int idx = blockIdx.x * blockDim.x + threadIdx.x;  // over 3*DD*DD (t,i,o)
    if (idx >= 3 * DD * DD) return;
    int o = idx % DD;
    int i = (idx / DD) % DD;
    int t = idx / (DD * DD);
    g_convw[((0 * 3 + t) * DD + i) * DD + o] = w1[(o * DD + i) * 3 + t];
    g_convw[((1 * 3 + t) * DD + i) * DD + o] = w2[(o * DD + i) * 3 + t];
    g_convw[((2 * 3 + t) * DD + i) * DD + o] = w3[(o * DD + i) * 3 + t];
}

__global__ void zero_stats_hg() {
    int i = blockIdx.x * blockDim.x + threadIdx.x;
    if (i < 12 * DD) g_stats[i] = 0.f;
    if (i < BBG * 3 * DD) g_hg[i] = 0.f;
}

// ---------------- CSR build (per launch; deterministic enough: fp sums within tol) ----
__global__ void zero_degcur() {
    int i = blockIdx.x * blockDim.x + threadIdx.x;
    if (i < NN) { g_deg[i] = 0; g_cur[i] = 0; }
}

__global__ void hist_dst(const int* __restrict__ dst) {
    int e = blockIdx.x * blockDim.x + threadIdx.x;
    if (e < EE) atomicAdd(&g_deg[dst[e]], 1);
}

__global__ void scan1() {  // 128 blocks x 1024
    __shared__ int sm[1024];
    int t = threadIdx.x;
    int i = blockIdx.x * 1024 + t;
    int v = g_deg[i];
    sm[t] = v;
    __syncthreads();
    for (int d = 1; d < 1024; d <<= 1) {
        int tmp = (t >= d) ? sm[t - d] : 0;
        __syncthreads();
        sm[t] += tmp;
        __syncthreads();
    }
    g_off[i] = sm[t] - v;  // exclusive within block
    if (t == 1023) g_part[blockIdx.x] = sm[1023];
}

__global__ void scan2() {  // 1 block x 128
    __shared__ int sm[128];
    int t = threadIdx.x;
    int v = g_part[t];
    sm[t] = v;
    __syncthreads();
    for (int d = 1; d < 128; d <<= 1) {
        int tmp = (t >= d) ? sm[t - d] : 0;
        __syncthreads();
        sm[t] += tmp;
        __syncthreads();
    }
    g_part[t] = sm[t] - v;  // exclusive block offsets
    if (t == 0) g_off[NN] = EE;
}

__global__ void scan3() {  // 128 blocks x 1024
    int i = blockIdx.x * 1024 + threadIdx.x;
    g_off[i] += g_part[blockIdx.x];
}

__global__ void csr_fill(const int* __restrict__ src, const int* __restrict__ dst,
                         const float* __restrict__ ew) {
    int e = blockIdx.x * blockDim.x + threadIdx.x;
    if (e >= EE) return;
    int d = dst[e];
    int pos = g_off[d] + atomicAdd(&g_cur[d], 1);
    g_meta[pos] = make_uint2((unsigned)src[e], __float_as_uint(ew[e]));
}

// ---------------- warp-per-node gather aggregation (no atomics, no zeroing) ----------
__global__ __launch_bounds__(256) void agg_gather(const float* __restrict__ H,
                                                  float* __restrict__ agg) {
    int node = blockIdx.x * 8 + (threadIdx.x >> 5);
    int lane = threadIdx.x & 31;
    int beg = g_off[node], end = g_off[node + 1];
    float4 acc = make_float4(0.f, 0.f, 0.f, 0.f);
    for (int b = beg; b < end; b += 32) {
        int n = min(32, end - b);
        uint2 m = (b + lane < end) ? g_meta[b + lane] : make_uint2(0u, 0u);
#pragma unroll 4
        for (int j = 0; j < n; j++) {
            int s = __shfl_sync(0xffffffffu, (int)m.x, j);
            float w = __int_as_float(__shfl_sync(0xffffffffu, (int)m.y, j));
            float4 v = __ldg(((const float4*)H) + s * 32 + lane);
            acc.x = fmaf(v.x, w, acc.x);
            acc.y = fmaf(v.y, w, acc.y);
            acc.z = fmaf(v.z, w, acc.z);
            acc.w = fmaf(v.w, w, acc.w);
        }
    }
    ((float4*)agg)[node * 32 + lane] = acc;
}

// ---------------- packed f32x2 GEMM core ----------------
__device__ __forceinline__ void mm_chunk(const float* __restrict__ sA,
                                         const float* __restrict__ sB,
                                         unsigned long long acc[8][4],
                                         int r0, int c0) {
#pragma unroll 8
    for (int k = 0; k < 64; k++) {
        ulonglong2 b01 = *(const ulonglong2*)(sB + k * 128 + c0);
        ulonglong2 b23 = *(const ulonglong2*)(sB + k * 128 + c0 + 4);
        unsigned long long bp0 = b01.x, bp1 = b01.y, bp2 = b23.x, bp3 = b23.y;
#pragma unroll
        for (int i = 0; i < 8; i++) {
            float a = sA[(r0 + i) * SA_S + k];
            unsigned long long aa;
            asm("mov.b64 %0, {%1, %1};" : "=l"(aa) : "f"(a));
            asm("fma.rn.f32x2 %0, %1, %2, %0;" : "+l"(acc[i][0]) : "l"(aa), "l"(bp0));
            asm("fma.rn.f32x2 %0, %1, %2, %0;" : "+l"(acc[i][1]) : "l"(aa), "l"(bp1));
            asm("fma.rn.f32x2 %0, %1, %2, %0;" : "+l"(acc[i][2]) : "l"(aa), "l"(bp2));
            asm("fma.rn.f32x2 %0, %1, %2, %0;" : "+l"(acc[i][3]) : "l"(aa), "l"(bp3));
        }
    }
}

__device__ __forceinline__ void load_sA(float* __restrict__ sA,
                                        const float* __restrict__ A,
                                        int base_row, int k0, int tid) {
#pragma unroll
    for (int p = 0; p < 8; p++) {
        int idx = p * 256 + tid;
        int row = idx >> 4, kq = idx & 15;
        float4 v = ((const float4*)(A + (base_row + row) * DD + k0))[kq];
        *(float4*)(sA + row * SA_S + kq * 4) = v;
    }
}

__device__ __forceinline__ void load_sA_g(float* __restrict__ sA,
                                          const float* __restrict__ A,
                                          int base_row, int k0, int tid) {
#pragma unroll
    for (int p = 0; p < 8; p++) {
        int idx = p * 256 + tid;
        int row = idx >> 4, kq = idx & 15;
        int gr = base_row + row;
        float4 v = make_float4(0.f, 0.f, 0.f, 0.f);
        if (gr >= 0 && gr < NN) v = ((const float4*)(A + gr * DD + k0))[kq];
        *(float4*)(sA + row * SA_S + kq * 4) = v;
    }
}

__device__ __forceinline__ void load_sB(float* __restrict__ sB,
                                        const float* __restrict__ W,
                                        int k0, int tid) {
#pragma unroll
    for (int p = 0; p < 8; p++) {
        int idx = p * 256 + tid;
        int kr = idx >> 5, c4 = idx & 31;
        ((float4*)(sB + kr * 128))[c4] = ((const float4*)(W + (k0 + kr) * DD))[c4];
    }
}

__device__ __forceinline__ void epilogue(unsigned long long acc[8][4],
                                         const float* __restrict__ bias,
                                         float* __restrict__ out,
                                         int base, int r0, int c0, int relu) {
    float4 bv0 = *(const float4*)(bias + c0);
    float4 bv1 = *(const float4*)(bias + c0 + 4);
    float bb[8] = {bv0.x, bv0.y, bv0.z, bv0.w, bv1.x, bv1.y, bv1.z, bv1.w};
#pragma unroll
    for (int i = 0; i < 8; i++) {
        float v[8];
#pragma unroll
        for (int j = 0; j < 4; j++) {
            float lo, hi;
            asm("mov.b64 {%0, %1}, %2;" : "=f"(lo), "=f"(hi) : "l"(acc[i][j]));
            v[2 * j] = lo; v[2 * j + 1] = hi;
        }
        float4 o0, o1;
        if (relu) {
            o0.x = fmaxf(v[0] + bb[0], 0.f); o0.y = fmaxf(v[1] + bb[1], 0.f);
            o0.z = fmaxf(v[2] + bb[2], 0.f); o0.w = fmaxf(v[3] + bb[3], 0.f);
            o1.x = fmaxf(v[4] + bb[4], 0.f); o1.y = fmaxf(v[5] + bb[5], 0.f);
            o1.z = fmaxf(v[6] + bb[6], 0.f); o1.w = fmaxf(v[7] + bb[7], 0.f);
        } else {
            o0.x = v[0] + bb[0]; o0.y = v[1] + bb[1];
            o0.z = v[2] + bb[2]; o0.w = v[3] + bb[3];
            o1.x = v[4] + bb[4]; o1.y = v[5] + bb[5];
            o1.z = v[6] + bb[6]; o1.w = v[7] + bb[7];
        }
        float* po = out + (base + r0 + i) * DD + c0;
        ((float4*)po)[0] = o0;
        ((float4*)(po + 4))[0] = o1;
    }
}

__global__ __launch_bounds__(256, 2) void gemm128_f2(
    const float* __restrict__ A, const float* __restrict__ W,
    const float* __restrict__ bias, float* __restrict__ out, int relu) {
    extern __shared__ float sm[];
    float* sA = sm;
    float* sB = sm + 128 * SA_S;
    const int tid = threadIdx.x;
    const int base = blockIdx.x * 128;
    const int ty = tid >> 4, tx = tid & 15;
    const int r0 = ty * 8, c0 = tx * 8;

    unsigned long long acc[8][4];
#pragma unroll
    for (int i = 0; i < 8; i++)
#pragma unroll
        for (int j = 0; j < 4; j++) acc[i][j] = 0ull;

#pragma unroll
    for (int kc = 0; kc < 2; kc++) {
        load_sA(sA, A, base, kc * 64, tid);
        load_sB(sB, W, kc * 64, tid);
        __syncthreads();
        mm_chunk(sA, sB, acc, r0, c0);
        __syncthreads();
    }
    epilogue(acc, bias, out, base, r0, c0, relu);
}

__global__ __launch_bounds__(256, 2) void conv128_f2(
    const float* __restrict__ X, const float* __restrict__ W3,
    const float* __restrict__ bias, float* __restrict__ out, int dil) {
    extern __shared__ float sm[];
    float* sA = sm;
    float* sB = sm + 128 * SA_S;
    const int tid = threadIdx.x;
    const int base = blockIdx.x * 128;
    const int ty = tid >> 4, tx = tid & 15;
    const int r0 = ty * 8, c0 = tx * 8;

    unsigned long long acc[8][4];
#pragma unroll
    for (int i = 0; i < 8; i++)
#pragma unroll
        for (int j = 0; j < 4; j++) acc[i][j] = 0ull;

    for (int tp = 0; tp < 3; tp++) {
        const int shift = (tp - 1) * dil;
        const float* Wt = W3 + tp * DD * DD;
#pragma unroll
        for (int kc = 0; kc < 2; kc++) {
            load_sA_g(sA, X, base + shift, kc * 64, tid);
            load_sB(sB, Wt, kc * 64, tid);
            __syncthreads();
            mm_chunk(sA, sB, acc, r0, c0);
            __syncthreads();
        }
    }
    epilogue(acc, bias, out, base, r0, c0, 0);
}

// ---------------- BN stats / apply ----------------
__global__ void bn3_stats(const float* __restrict__ c1, const float* __restrict__ c2,
                          const float* __restrict__ c3) {
    const int ch = threadIdx.x;
    const int rows = NN / 512;
    const int r0 = blockIdx.x * rows;
    float s1 = 0, q1 = 0, s2 = 0, q2 = 0, s3 = 0, q3 = 0;
    for (int r = r0; r < r0 + rows; r++) {
        int o = r * DD + ch;
        float v1 = c1[o], v2 = c2[o], v3 = c3[o];
        float x1 = fmaxf(v1, 0.f) + v2;
        float x2 = fmaxf(v2, 0.f) + v3;
        float x3 = fmaxf(v3, 0.f) + v1;
        s1 += x1; q1 = fmaf(x1, x1, q1);
        s2 += x2; q2 = fmaf(x2, x2, q2);
        s3 += x3; q3 = fmaf(x3, x3, q3);
    }
    atomicAdd(&g_stats[0 * DD + ch], s1); atomicAdd(&g_stats[1 * DD + ch], q1);
    atomicAdd(&g_stats[2 * DD + ch], s2); atomicAdd(&g_stats[3 * DD + ch], q2);
    atomicAdd(&g_stats[4 * DD + ch], s3); atomicAdd(&g_stats[5 * DD + ch], q3);
}

__global__ void bn3_apply(float* __restrict__ c1, float* __restrict__ c2,
                          float* __restrict__ c3, const float* __restrict__ g,
                          const float* __restrict__ b) {
    int idx = blockIdx.x * blockDim.x + threadIdx.x;
    int ch = idx & (DD - 1);
    float v1 = c1[idx], v2 = c2[idx], v3 = c3[idx];
    float x1 = fmaxf(v1, 0.f) + v2;
    float x2 = fmaxf(v2, 0.f) + v3;
    float x3 = fmaxf(v3, 0.f) + v1;
    const float inv = 1.f / (float)NN;
    float mu1 = g_stats[0 * DD + ch] * inv;
    float va1 = g_stats[1 * DD + ch] * inv - mu1 * mu1;
    float mu2 = g_stats[2 * DD + ch] * inv;
    float va2 = g_stats[3 * DD + ch] * inv - mu2 * mu2;
    float mu3 = g_stats[4 * DD + ch] * inv;
    float va3 = g_stats[5 * DD + ch] * inv - mu3 * mu3;
    float gg = g[ch], bb = b[ch];
    c1[idx] = (x1 - mu1) * rsqrtf(va1 + EPSV) * gg + bb;
    c2[idx] = (x2 - mu2) * rsqrtf(va2 + EPSV) * gg + bb;
    c3[idx] = (x3 - mu3) * rsqrtf(va3 + EPSV) * gg + bb;
}

__global__ void bn1_stats(const float* __restrict__ x) {
    const int ch = threadIdx.x;
    const int rows = NN / 512;
    const int r0 = blockIdx.x * rows;
    float s = 0, q = 0;
    for (int r = r0; r < r0 + rows; r++) {
        float v = x[r * DD + ch];
        s += v; q = fmaf(v, v, q);
    }
    atomicAdd(&g_stats[ch], s);
    atomicAdd(&g_stats[DD + ch], q);
}

__global__ void bn1_apply(float* __restrict__ x, const float* __restrict__ g,
                          const float* __restrict__ b) {
    int idx = blockIdx.x * blockDim.x + threadIdx.x;
    int ch = idx & (DD - 1);
    const float inv = 1.f / (float)NN;
    float mu = g_stats[ch] * inv;
    float va = g_stats[DD + ch] * inv - mu * mu;
    x[idx] = (x[idx] - mu) * rsqrtf(va + EPSV) * g[ch] + b[ch];
}

// ---------------- press conv (1,3,3) over channel/spatial dims ----------------
__global__ void press_kernel(const float* __restrict__ a1, const float* __restrict__ a2,
                             const float* __restrict__ a3, const float* __restrict__ pw,
                             const float* __restrict__ pb, float* __restrict__ out) {
    int idx = blockIdx.x * blockDim.x + threadIdx.x;
    int n = idx >> 7, d = idx & 127;
    float w00 = pw[0], w01 = pw[1], w02 = pw[2];
    float w10 = pw[3], w11 = pw[4], w12 = pw[5];
    float w20 = pw[6], w21 = pw[7], w22 = pw[8];
    const float* p1 = a1 + n * DD;
    const float* p2 = a2 + n * DD;
    const float* p3 = a3 + n * DD;
    float acc = pb[0];
    if (d > 0) acc += w00 * p1[d - 1] + w10 * p2[d - 1] + w20 * p3[d - 1];
    acc += w01 * p1[d] + w11 * p2[d] + w21 * p3[d];
    if (d < 127) acc += w02 * p1[d + 1] + w12 * p2[d + 1] + w22 * p3[d + 1];
    out[idx] = acc;
}

// ---------------- per-graph pooling (node_gid sorted) ----------------
__global__ void pool_kernel(const float* __restrict__ h2, const float* __restrict__ h3,
                            const float* __restrict__ h4, const int* __restrict__ gid) {
    const int ch = threadIdx.x;
    const int rows = NN / 512;
    const int r0 = blockIdx.x * rows;
    int cur = gid[r0];
    float s2 = 0, s3 = 0, s4 = 0;
    for (int r = r0; r < r0 + rows; r++) {
        int g = gid[r];
        if (g != cur) {
            atomicAdd(&g_hg[cur * 3 * DD + ch], s2);
            atomicAdd(&g_hg[cur * 3 * DD + DD + ch], s3);
            atomicAdd(&g_hg[cur * 3 * DD + 2 * DD + ch], s4);
            s2 = s3 = s4 = 0;
            cur = g;
        }
        int o = r * DD + ch;
        s2 += h2[o]; s3 += h3[o]; s4 += h4[o];
    }
    atomicAdd(&g_hg[cur * 3 * DD + ch], s2);
    atomicAdd(&g_hg[cur * 3 * DD + DD + ch], s3);
    atomicAdd(&g_hg[cur * 3 * DD + 2 * DD + ch], s4);
}

// ---------------- final classifier ----------------
__global__ void classify(const float* __restrict__ cl1w, const float* __restrict__ cl1b,
                         const float* __restrict__ cl2w, const float* __restrict__ cl2b,
                         float* __restrict__ out) {
    __shared__ float mid[DD];
    int t = threadIdx.x;
    for (int b = 0; b < BBG; b++) {
        float acc = cl1b[t];
        for (int k = 0; k < 3 * DD; k++) acc = fmaf(g_hg[b * 3 * DD + k], cl1w[t * 3 * DD + k], acc);
        mid[t] = acc;
        __syncthreads();
        if (t < 5) {
            float o = cl2b[t];
            for (int k = 0; k < DD; k++) o = fmaf(mid[k], cl2w[t * DD + k], o);
            out[b * 5 + t] = o;
        }
        __syncthreads();
    }
}

// ---------------- host launch ----------------
extern "C" void kernel_launch(void* const* d_in, const int* in_sizes, int n_in,
                              void* d_out, int out_size) {
    int o = (in_sizes[5] == 1) ? 6 : 5;
    const float* h   = (const float*)d_in[0];
    const float* ew  = (const float*)d_in[1];
    const int*   src = (const int*)d_in[2];
    const int*   dst = (const int*)d_in[3];
    const int*   gid = (const int*)d_in[4];
    const float* c1w = (const float*)d_in[o + 0];
    const float* c1b = (const float*)d_in[o + 1];
    const float* c2w = (const float*)d_in[o + 2];
    const float* c2b = (const float*)d_in[o + 3];
    const float* c3w = (const float*)d_in[o + 4];
    const float* c3b = (const float*)d_in[o + 5];
    const float* pw  = (const float*)d_in[o + 6];
    const float* pb  = (const float*)d_in[o + 7];
    const float* g11w = (const float*)d_in[o + 8];
    const float* g11b = (const float*)d_in[o + 9];
    const float* g12w = (const float*)d_in[o + 10];
    const float* g12b = (const float*)d_in[o + 11];
    const float* g13w = (const float*)d_in[o + 12];
    const float* g13b = (const float*)d_in[o + 13];
    const float* g2w  = (const float*)d_in[o + 14];
    const float* g2b  = (const float*)d_in[o + 15];
    const float* g3w  = (const float*)d_in[o + 16];
    const float* g3b  = (const float*)d_in[o + 17];
    const float* g4w  = (const float*)d_in[o + 18];
    const float* g4b  = (const float*)d_in[o + 19];
    const float* bng  = (const float*)d_in[o + 20];
    const float* bnb  = (const float*)d_in[o + 21];
    const float* cl1w = (const float*)d_in[o + 22];
    const float* cl1b = (const float*)d_in[o + 23];
    const float* cl2w = (const float*)d_in[o + 24];
    const float* cl2b = (const float*)d_in[o + 25];
    float* out = (float*)d_out;

    float *A, *B, *C, *a1, *a2, *a3, *agg, *convw;
    cudaGetSymbolAddress((void**)&A, g_A);
    cudaGetSymbolAddress((void**)&B, g_B);
    cudaGetSymbolAddress((void**)&C, g_C);
    cudaGetSymbolAddress((void**)&a1, g_a1);
    cudaGetSymbolAddress((void**)&a2, g_a2);
    cudaGetSymbolAddress((void**)&a3, g_a3);
    cudaGetSymbolAddress((void**)&agg, g_agg);
    cudaGetSymbolAddress((void**)&convw, g_convw);

    const int MM_SMEM = (128 * SA_S + 64 * 128) * 4;
    cudaFuncSetAttribute(gemm128_f2, cudaFuncAttributeMaxDynamicSharedMemorySize, MM_SMEM);
    cudaFuncSetAttribute(conv128_f2, cudaFuncAttributeMaxDynamicSharedMemorySize, MM_SMEM);

    // ---- CSR build (once per launch, reused by all 6 graph convs) ----
    zero_degcur<<<NN / 512, 512>>>();
    hist_dst<<<EE / 512, 512>>>(dst);
    scan1<<<128, 1024>>>();
    scan2<<<1, 128>>>();
    scan3<<<128, 1024>>>();
    csr_fill<<<EE / 512, 512>>>(src, dst, ew);

    // ---- dense front-end ----
    prep_conv_w<<<(3 * DD * DD + 255) / 256, 256>>>(c1w, c2w, c3w);
    conv128_f2<<<NN / 128, 256, MM_SMEM>>>(h, convw + 0 * 3 * DD * DD, c1b, A, 1);
    conv128_f2<<<NN / 128, 256, MM_SMEM>>>(h, convw + 1 * 3 * DD * DD, c2b, B, 2);
    conv128_f2<<<NN / 128, 256, MM_SMEM>>>(h, convw + 2 * 3 * DD * DD, c3b, C, 3);

    zero_stats_hg<<<24, 256>>>();
    bn3_stats<<<512, DD>>>(A, B, C);
    bn3_apply<<<NN * DD / 256, 256>>>(A, B, C, bng, bnb);

#define GCONV(IN, W, BIAS, OUT)                                        \
    agg_gather<<<NN / 8, 256>>>(IN, agg);                              \
    gemm128_f2<<<NN / 128, 256, MM_SMEM>>>(agg, W, BIAS, OUT, 1);

    GCONV(A, g11w, g11b, a1)
    GCONV(B, g12w, g12b, a2)
    GCONV(C, g13w, g13b, a3)

    press_kernel<<<NN * DD / 256, 256>>>(a1, a2, a3, pw, pb, A);
    zero_stats_hg<<<24, 256>>>();
    bn1_stats<<<512, DD>>>(A);
    bn1_apply<<<NN * DD / 256, 256>>>(A, bng, bnb);

    GCONV(A, g2w, g2b, B)   // ac_h2
    GCONV(B, g3w, g3b, C)   // ac_h3
    GCONV(C, g4w, g4b, a1)  // ac_h4

    pool_kernel<<<512, DD>>>(B, C, a1, gid);
    classify<<<1, DD>>>(cl1w, cl1b, cl2w, cl2b, out);
#undef GCONV
}